// round 1
// baseline (speedup 1.0000x reference)
#include <cuda_runtime.h>
#include <math.h>

#define NTOK 401
#define NPT  400
#define DIMM 512
#define NHEAD 8
#define HDIM 64
#define QKV3 1536
#define CPBH 512
#define NPAIR (NTOK*NTOK)
#define FLAG_RELU 1
#define FLAG_ADD  2

// ---------------- scratch (alloc-free, __device__ globals) ----------------
__device__ float  g_h[NTOK*DIMM];        // residual stream
__device__ float  g_ln[NTOK*DIMM];       // layernorm output
__device__ float  g_qkv[NTOK*QKV3];      // fused qkv
__device__ float  g_attn[NHEAD*NTOK*NTOK]; // attention logits / probs (5.1 MB)
__device__ float  g_ao[NTOK*DIMM];       // attention output (pre-proj)
__device__ float2 g_dir[NPAIR];          // normalized pair directions
__device__ float  g_coords[NTOK*2];

// ---------------- small helpers ----------------
__device__ __forceinline__ float2 blockReduce2_256(float a, float b) {
    __shared__ float sa[8], sb[8];
    __syncthreads();
    #pragma unroll
    for (int o = 16; o > 0; o >>= 1) {
        a += __shfl_xor_sync(0xffffffffu, a, o);
        b += __shfl_xor_sync(0xffffffffu, b, o);
    }
    int w = threadIdx.x >> 5;
    if ((threadIdx.x & 31) == 0) { sa[w] = a; sb[w] = b; }
    __syncthreads();
    a = sa[0]+sa[1]+sa[2]+sa[3]+sa[4]+sa[5]+sa[6]+sa[7];
    b = sb[0]+sb[1]+sb[2]+sb[3]+sb[4]+sb[5]+sb[6]+sb[7];
    return make_float2(a, b);
}

// ---------------- setup: CLS row + coords (CLS coord = 0) ----------------
__global__ void setup_kernel(const float* __restrict__ cls,
                             const float* __restrict__ coords) {
    int t = blockIdx.x*blockDim.x + threadIdx.x;
    if (t < DIMM)  g_h[t] = cls[t];
    if (t < 2)     g_coords[t] = 0.f;
    if (t < NPT*2) g_coords[2+t] = coords[t];
}

// ---------------- normalized pair directions (shared by both layers) ------
__global__ void dirs_kernel() {
    int p = blockIdx.x*blockDim.x + threadIdx.x;
    if (p >= NPAIR) return;
    int i = p / NTOK, j = p - i*NTOK;
    float dx = g_coords[2*i]   - g_coords[2*j];
    float dy = g_coords[2*i+1] - g_coords[2*j+1];
    float n  = sqrtf(dx*dx + dy*dy);
    float inv = 1.f/(n + 1e-6f);
    g_dir[p] = make_float2(dx*inv, dy*inv);
}

// ---------------- generic fp32 GEMM: C = A[M,K] @ B[K,N] + bias -----------
// flags: bit0 relu, bit1 add-to-existing-C. Requires K%16==0, N%64==0.
__global__ void gemm_kernel(const float* __restrict__ A, const float* __restrict__ B,
                            const float* __restrict__ bias, float* __restrict__ C,
                            int M, int N, int K, int flags) {
    __shared__ float As[16][68];
    __shared__ float Bs[16][64];
    int t  = threadIdx.x;                // 256 threads
    int m0 = blockIdx.y << 6, n0 = blockIdx.x << 6;
    int tx = t & 15, ty = t >> 4;
    int arow = t >> 2, acol = (t & 3) << 2;
    int brow = t >> 4, bcol = (t & 15) << 2;
    float acc[4][4] = {};
    for (int k0 = 0; k0 < K; k0 += 16) {
        float4 av = make_float4(0.f,0.f,0.f,0.f);
        if (m0 + arow < M)
            av = *(const float4*)(A + (size_t)(m0+arow)*K + k0 + acol);
        As[acol  ][arow] = av.x; As[acol+1][arow] = av.y;
        As[acol+2][arow] = av.z; As[acol+3][arow] = av.w;
        *(float4*)(&Bs[brow][bcol]) =
            *(const float4*)(B + (size_t)(k0+brow)*N + n0 + bcol);
        __syncthreads();
        #pragma unroll
        for (int k = 0; k < 16; k++) {
            float4 a4 = *(const float4*)(&As[k][ty<<2]);
            float4 b4 = *(const float4*)(&Bs[k][tx<<2]);
            float avv[4] = {a4.x,a4.y,a4.z,a4.w};
            float bvv[4] = {b4.x,b4.y,b4.z,b4.w};
            #pragma unroll
            for (int i = 0; i < 4; i++)
                #pragma unroll
                for (int j = 0; j < 4; j++)
                    acc[i][j] = fmaf(avv[i], bvv[j], acc[i][j]);
        }
        __syncthreads();
    }
    #pragma unroll
    for (int i = 0; i < 4; i++) {
        int m = m0 + (ty<<2) + i;
        if (m >= M) break;
        #pragma unroll
        for (int j = 0; j < 4; j++) {
            int n = n0 + (tx<<2) + j;
            float v = acc[i][j] + bias[n];
            if (flags & FLAG_RELU) v = fmaxf(v, 0.f);
            if (flags & FLAG_ADD)  v += C[(size_t)m*N + n];
            C[(size_t)m*N + n] = v;
        }
    }
}

// ---------------- layernorm (one block per row) ----------------
__global__ void ln_kernel(const float* __restrict__ x, float* __restrict__ y,
                          const float* __restrict__ g, const float* __restrict__ b) {
    int row = blockIdx.x, t = threadIdx.x;     // 256 threads
    const float* xr = x + (size_t)row*DIMM;
    float v0 = xr[t], v1 = xr[t+256];
    float2 s = blockReduce2_256(v0+v1, v0*v0+v1*v1);
    float mean = s.x * (1.f/512.f);
    float inv  = rsqrtf(s.y*(1.f/512.f) - mean*mean + 1e-5f);
    y[(size_t)row*DIMM + t]       = (v0-mean)*inv*g[t]     + b[t];
    y[(size_t)row*DIMM + t + 256] = (v1-mean)*inv*g[t+256] + b[t+256];
}

// ---------------- QK^T scores (per-head 32x32 tiles) ----------------
__global__ void scores_kernel() {
    __shared__ float sq[32][65];
    __shared__ float sk[32][65];
    int h  = blockIdx.z;
    int i0 = blockIdx.y << 5, j0 = blockIdx.x << 5;
    int t  = threadIdx.x;                 // 256 threads
    int r = t >> 3, c = (t & 7) << 3;
    {
        const float* qp = g_qkv + (size_t)(i0+r)*QKV3 + h*HDIM + c;
        const float* kp = g_qkv + (size_t)(j0+r)*QKV3 + DIMM + h*HDIM + c;
        bool qi = (i0 + r < NTOK), ki = (j0 + r < NTOK);
        #pragma unroll
        for (int q = 0; q < 8; q++) sq[r][c+q] = qi ? qp[q] : 0.f;
        #pragma unroll
        for (int q = 0; q < 8; q++) sk[r][c+q] = ki ? kp[q] : 0.f;
    }
    __syncthreads();
    int tx = t & 31, ty = t >> 5;        // ty in 0..7
    float acc[4] = {0.f,0.f,0.f,0.f};
    #pragma unroll
    for (int d = 0; d < 64; d++) {
        float kv = sk[tx][d];
        acc[0] = fmaf(sq[ty     ][d], kv, acc[0]);
        acc[1] = fmaf(sq[ty +  8][d], kv, acc[1]);
        acc[2] = fmaf(sq[ty + 16][d], kv, acc[2]);
        acc[3] = fmaf(sq[ty + 24][d], kv, acc[3]);
    }
    int j = j0 + tx;
    if (j < NTOK) {
        #pragma unroll
        for (int ii = 0; ii < 4; ii++) {
            int i = i0 + ty + (ii<<3);
            if (i < NTOK)
                g_attn[((size_t)h*NTOK + i)*NTOK + j] = 0.125f*acc[ii];
        }
    }
}

// ---------------- CPB bias MLP, lane-per-pair, weights in SMEM ----------
__global__ void cpb_kernel(const float* __restrict__ w1, const float* __restrict__ b1,
                           const float* __restrict__ w2, const float* __restrict__ b2) {
    __shared__ float swx[CPBH], swy[CPBH], sbb[CPBH];
    __shared__ float sw2[CPBH*8];
    int t = threadIdx.x;                  // 256 threads
    for (int c = t; c < CPBH; c += 256) {
        swx[c] = w1[c]; swy[c] = w1[CPBH + c]; sbb[c] = b1[c];
    }
    for (int c = t; c < CPBH*8; c += 256) sw2[c] = w2[c];
    __syncthreads();

    int p = blockIdx.x*256 + t;
    if (p >= NPAIR) return;
    float2 dv = g_dir[p];
    float ux = dv.x, uy = dv.y;
    float acc[8] = {0.f,0.f,0.f,0.f,0.f,0.f,0.f,0.f};
    #pragma unroll 8
    for (int c = 0; c < CPBH; c++) {
        float hv = fmaf(ux, swx[c], fmaf(uy, swy[c], sbb[c]));
        hv = fmaxf(hv, 0.f);
        float4 wa = *(const float4*)(sw2 + (c<<3));
        float4 wb = *(const float4*)(sw2 + (c<<3) + 4);
        acc[0] = fmaf(hv, wa.x, acc[0]);
        acc[1] = fmaf(hv, wa.y, acc[1]);
        acc[2] = fmaf(hv, wa.z, acc[2]);
        acc[3] = fmaf(hv, wa.w, acc[3]);
        acc[4] = fmaf(hv, wb.x, acc[4]);
        acc[5] = fmaf(hv, wb.y, acc[5]);
        acc[6] = fmaf(hv, wb.z, acc[6]);
        acc[7] = fmaf(hv, wb.w, acc[7]);
    }
    int i = p / NTOK;
    int j = p - i*NTOK;
    size_t base = (size_t)i*NTOK + j;
    #pragma unroll
    for (int k = 0; k < 8; k++)
        g_attn[(size_t)k*NTOK*NTOK + base] += acc[k] + b2[k];
}

// ---------------- softmax over j, one block per (h,i) row ----------------
__global__ void softmax_kernel() {
    int row = blockIdx.x;                 // h*NTOK + i
    float* a = g_attn + (size_t)row*NTOK;
    int t = threadIdx.x;                  // 128 threads
    float vals[4];
    float mx = -1e30f;
    #pragma unroll
    for (int q = 0; q < 4; q++) {
        int j = t + q*128;
        vals[q] = (j < NTOK) ? a[j] : -1e30f;
        mx = fmaxf(mx, vals[q]);
    }
    #pragma unroll
    for (int o = 16; o > 0; o >>= 1)
        mx = fmaxf(mx, __shfl_xor_sync(0xffffffffu, mx, o));
    __shared__ float sm[4];
    if ((t & 31) == 0) sm[t >> 5] = mx;
    __syncthreads();
    mx = fmaxf(fmaxf(sm[0], sm[1]), fmaxf(sm[2], sm[3]));

    float s = 0.f;
    #pragma unroll
    for (int q = 0; q < 4; q++) {
        int j = t + q*128;
        if (j < NTOK) { vals[q] = __expf(vals[q] - mx); s += vals[q]; }
    }
    #pragma unroll
    for (int o = 16; o > 0; o >>= 1)
        s += __shfl_xor_sync(0xffffffffu, s, o);
    __shared__ float ss[4];
    if ((t & 31) == 0) ss[t >> 5] = s;
    __syncthreads();
    s = ss[0] + ss[1] + ss[2] + ss[3];
    float inv = 1.f / s;
    #pragma unroll
    for (int q = 0; q < 4; q++) {
        int j = t + q*128;
        if (j < NTOK) a[j] = vals[q] * inv;
    }
}

// ---------------- attn @ V  (per-head, 32 i-rows per block) ----------------
__global__ void av_kernel() {
    __shared__ float sa[32][33];
    __shared__ float sv[32][65];
    int h  = blockIdx.y;
    int i0 = blockIdx.x << 5;
    int t  = threadIdx.x;                 // 256 threads
    int d = t & 63, il = t >> 6;          // il in 0..3
    int ar = t >> 3, ac = (t & 7) << 2;
    int vr = t >> 3, vc = (t & 7) << 3;
    float acc[8] = {0.f,0.f,0.f,0.f,0.f,0.f,0.f,0.f};
    for (int j0 = 0; j0 < NTOK; j0 += 32) {
        #pragma unroll
        for (int q = 0; q < 4; q++) {
            int i = i0 + ar, j = j0 + ac + q;
            sa[ar][ac+q] = (i < NTOK && j < NTOK)
                         ? g_attn[((size_t)h*NTOK + i)*NTOK + j] : 0.f;
        }
        const float* vp = g_qkv + (size_t)(j0+vr)*QKV3 + 2*DIMM + h*HDIM + vc;
        bool vi = (j0 + vr < NTOK);
        #pragma unroll
        for (int q = 0; q < 8; q++) sv[vr][vc+q] = vi ? vp[q] : 0.f;
        __syncthreads();
        #pragma unroll
        for (int j = 0; j < 32; j++) {
            float vv = sv[j][d];
            #pragma unroll
            for (int ii = 0; ii < 8; ii++)
                acc[ii] = fmaf(sa[il + (ii<<2)][j], vv, acc[ii]);
        }
        __syncthreads();
    }
    #pragma unroll
    for (int ii = 0; ii < 8; ii++) {
        int i = i0 + il + (ii<<2);
        if (i < NTOK) g_ao[(size_t)i*DIMM + h*HDIM + d] = acc[ii];
    }
}

// ---------------- final: LN(row 0) -> fc2 -> out[2] ----------------
__global__ void final_kernel(const float* __restrict__ g, const float* __restrict__ b,
                             const float* __restrict__ w, const float* __restrict__ bias,
                             float* __restrict__ out) {
    int t = threadIdx.x;                  // 256 threads
    float v0 = g_h[t], v1 = g_h[t+256];
    float2 s = blockReduce2_256(v0+v1, v0*v0+v1*v1);
    float mean = s.x * (1.f/512.f);
    float inv  = rsqrtf(s.y*(1.f/512.f) - mean*mean + 1e-5f);
    float l0 = (v0-mean)*inv*g[t]     + b[t];
    float l1 = (v1-mean)*inv*g[t+256] + b[t+256];
    float p0 = l0*w[t*2]   + l1*w[(t+256)*2];
    float p1 = l0*w[t*2+1] + l1*w[(t+256)*2+1];
    float2 sp = blockReduce2_256(p0, p1);
    if (t == 0) { out[0] = sp.x + bias[0]; out[1] = sp.y + bias[1]; }
}

// ---------------- launch ----------------
extern "C" void kernel_launch(void* const* d_in, const int* in_sizes, int n_in,
                              void* d_out, int out_size) {
    const float* h_in   = (const float*)d_in[0];
    const float* coords = (const float*)d_in[1];
    const float* fc1_w  = (const float*)d_in[2];
    const float* fc1_b  = (const float*)d_in[3];
    const float* cls    = (const float*)d_in[4];
    const float* norm_g = (const float*)d_in[25];
    const float* norm_b = (const float*)d_in[26];
    const float* fc2_w  = (const float*)d_in[27];
    const float* fc2_b  = (const float*)d_in[28];

    float *p_h, *p_ln, *p_qkv, *p_ao;
    cudaGetSymbolAddress((void**)&p_h,   g_h);
    cudaGetSymbolAddress((void**)&p_ln,  g_ln);
    cudaGetSymbolAddress((void**)&p_qkv, g_qkv);
    cudaGetSymbolAddress((void**)&p_ao,  g_ao);

    setup_kernel<<<4, 256>>>(cls, coords);
    dirs_kernel<<<(NPAIR + 255)/256, 256>>>();
    // fc1 + relu into rows 1..400 of residual stream
    gemm_kernel<<<dim3(DIMM/64, (NPT+63)/64), 256>>>(
        h_in, fc1_w, fc1_b, p_h + DIMM, NPT, DIMM, 1024, FLAG_RELU);

    for (int L = 0; L < 2; L++) {
        const float* lp[10];
        for (int q = 0; q < 10; q++) lp[q] = (const float*)d_in[5 + L*10 + q];
        const float* ln_g   = lp[0]; const float* ln_b   = lp[1];
        const float* cpb_w1 = lp[2]; const float* cpb_b1 = lp[3];
        const float* cpb_w2 = lp[4]; const float* cpb_b2 = lp[5];
        const float* qkv_w  = lp[6]; const float* qkv_b  = lp[7];
        const float* proj_w = lp[8]; const float* proj_b = lp[9];

        ln_kernel<<<NTOK, 256>>>(p_h, p_ln, ln_g, ln_b);
        gemm_kernel<<<dim3(QKV3/64, (NTOK+63)/64), 256>>>(
            p_ln, qkv_w, qkv_b, p_qkv, NTOK, QKV3, DIMM, 0);
        scores_kernel<<<dim3(13, 13, NHEAD), 256>>>();
        cpb_kernel<<<(NPAIR + 255)/256, 256>>>(cpb_w1, cpb_b1, cpb_w2, cpb_b2);
        softmax_kernel<<<NHEAD*NTOK, 128>>>();
        av_kernel<<<dim3(13, NHEAD), 256>>>();
        gemm_kernel<<<dim3(DIMM/64, (NTOK+63)/64), 256>>>(
            p_ao, proj_w, proj_b, p_h, NTOK, DIMM, DIMM, FLAG_ADD);
    }

    final_kernel<<<1, 256>>>(norm_g, norm_b, fc2_w, fc2_b, (float*)d_out);
}

// round 2
// speedup vs baseline: 1.2516x; 1.2516x over previous
#include <cuda_runtime.h>
#include <math.h>

#define NTOK 401
#define NPT  400
#define DIMM 512
#define NHEAD 8
#define HDIM 64
#define QKV3 1536
#define CPBH 512
#define NPAIR (NTOK*NTOK)
#define TABN 32768
#define PI_F 3.14159265358979323846f
#define FLAG_RELU 1
#define FLAG_ADD  2

// ---------------- scratch (alloc-free, __device__ globals) ----------------
__device__ float  g_h[NTOK*DIMM];          // residual stream
__device__ float  g_ln[NTOK*DIMM];         // layernorm output
__device__ float  g_qkv[NTOK*QKV3];        // fused qkv
__device__ float  g_attn[NHEAD*NTOK*NTOK]; // attention logits / probs (5.1 MB)
__device__ float  g_ao[NTOK*DIMM];         // attention output (pre-proj)
__device__ float  g_angpos[NPAIR];         // table position per pair (shared by layers)
__device__ float  g_coords[NTOK*2];
__device__ float  g_table[(TABN+4)*8];     // per-layer bias table (+2pi row, diag row, zero row)

// ---------------- small helpers ----------------
__device__ __forceinline__ float2 blockReduce2_256(float a, float b) {
    __shared__ float sa[8], sb[8];
    __syncthreads();
    #pragma unroll
    for (int o = 16; o > 0; o >>= 1) {
        a += __shfl_xor_sync(0xffffffffu, a, o);
        b += __shfl_xor_sync(0xffffffffu, b, o);
    }
    int w = threadIdx.x >> 5;
    if ((threadIdx.x & 31) == 0) { sa[w] = a; sb[w] = b; }
    __syncthreads();
    a = sa[0]+sa[1]+sa[2]+sa[3]+sa[4]+sa[5]+sa[6]+sa[7];
    b = sb[0]+sb[1]+sb[2]+sb[3]+sb[4]+sb[5]+sb[6]+sb[7];
    return make_float2(a, b);
}

// ---------------- setup: CLS row + coords (CLS coord = 0) ----------------
__global__ void setup_kernel(const float* __restrict__ cls,
                             const float* __restrict__ coords) {
    int t = blockIdx.x*blockDim.x + threadIdx.x;
    if (t < DIMM)  g_h[t] = cls[t];
    if (t < 2)     g_coords[t] = 0.f;
    if (t < NPT*2) g_coords[2+t] = coords[t];
}

// ---------------- per-pair angle table position (shared by both layers) ----
__global__ void angpos_kernel() {
    int p = blockIdx.x*blockDim.x + threadIdx.x;
    if (p >= NPAIR) return;
    int i = p / NTOK, j = p - i*NTOK;
    float pos;
    if (i == j) {
        pos = (float)(TABN + 1);           // diag: dir = (0,0) special row
    } else {
        float dx = g_coords[2*i]   - g_coords[2*j];
        float dy = g_coords[2*i+1] - g_coords[2*j+1];
        float th = atan2f(dy, dx);         // (-pi, pi]
        pos = (th + PI_F) * ((float)TABN / (2.0f*PI_F));
        pos = fminf(fmaxf(pos, 0.f), (float)TABN);
    }
    g_angpos[p] = pos;
}

// ---------------- build CPB bias table: rows 0..TABN angles, TABN+1 diag,
// ---------------- TABN+2 zeros. b2 folded in. --------------------------
__global__ void cpb_table_kernel(const float* __restrict__ w1, const float* __restrict__ b1,
                                 const float* __restrict__ w2, const float* __restrict__ b2) {
    __shared__ float swx[CPBH], swy[CPBH], sbb[CPBH];
    __shared__ float sw2[CPBH*8];
    int t = threadIdx.x;                  // 256 threads
    for (int c = t; c < CPBH; c += 256) {
        swx[c] = w1[c]; swy[c] = w1[CPBH + c]; sbb[c] = b1[c];
    }
    for (int c = t; c < CPBH*8; c += 256) sw2[c] = w2[c];
    __syncthreads();

    int idx = blockIdx.x*256 + t;
    if (idx > TABN + 2) return;
    float ux = 0.f, uy = 0.f;
    if (idx <= TABN) {
        float th = -PI_F + (2.0f*PI_F) * ((float)idx / (float)TABN);
        ux = cosf(th); uy = sinf(th);
    }
    float acc[8] = {0.f,0.f,0.f,0.f,0.f,0.f,0.f,0.f};
    #pragma unroll 8
    for (int c = 0; c < CPBH; c++) {
        float hv = fmaf(ux, swx[c], fmaf(uy, swy[c], sbb[c]));
        hv = fmaxf(hv, 0.f);
        float4 wa = *(const float4*)(sw2 + (c<<3));
        float4 wb = *(const float4*)(sw2 + (c<<3) + 4);
        acc[0] = fmaf(hv, wa.x, acc[0]);
        acc[1] = fmaf(hv, wa.y, acc[1]);
        acc[2] = fmaf(hv, wa.z, acc[2]);
        acc[3] = fmaf(hv, wa.w, acc[3]);
        acc[4] = fmaf(hv, wb.x, acc[4]);
        acc[5] = fmaf(hv, wb.y, acc[5]);
        acc[6] = fmaf(hv, wb.z, acc[6]);
        acc[7] = fmaf(hv, wb.w, acc[7]);
    }
    float* row = g_table + (size_t)idx*8;
    if (idx == TABN + 2) {
        #pragma unroll
        for (int k = 0; k < 8; k++) row[k] = 0.f;
    } else {
        #pragma unroll
        for (int k = 0; k < 8; k++) row[k] = acc[k] + b2[k];
    }
}

// ---------------- apply bias: lerp table, RMW 8 attn planes ----------------
__global__ void cpb_apply_kernel() {
    int p = blockIdx.x*256 + threadIdx.x;
    if (p >= NPAIR) return;
    float pos = g_angpos[p];
    int i0 = (int)pos;
    float f = pos - (float)i0;
    const float4* tp = (const float4*)(g_table + (size_t)i0*8);
    float4 a0 = tp[0], a1 = tp[1];        // row i0
    float4 c0 = tp[2], c1 = tp[3];        // row i0+1 (contiguous)
    float b[8];
    b[0] = a0.x + f*(c0.x - a0.x);
    b[1] = a0.y + f*(c0.y - a0.y);
    b[2] = a0.z + f*(c0.z - a0.z);
    b[3] = a0.w + f*(c0.w - a0.w);
    b[4] = a1.x + f*(c1.x - a1.x);
    b[5] = a1.y + f*(c1.y - a1.y);
    b[6] = a1.z + f*(c1.z - a1.z);
    b[7] = a1.w + f*(c1.w - a1.w);
    #pragma unroll
    for (int k = 0; k < 8; k++)
        g_attn[(size_t)k*NTOK*NTOK + p] += b[k];
}

// ---------------- generic fp32 GEMM: C = A[M,K] @ B[K,N] + bias -----------
// flags: bit0 relu, bit1 add-to-existing-C. Requires K%16==0, N%64==0.
__global__ void gemm_kernel(const float* __restrict__ A, const float* __restrict__ B,
                            const float* __restrict__ bias, float* __restrict__ C,
                            int M, int N, int K, int flags) {
    __shared__ float As[16][68];
    __shared__ float Bs[16][64];
    int t  = threadIdx.x;                // 256 threads
    int m0 = blockIdx.y << 6, n0 = blockIdx.x << 6;
    int tx = t & 15, ty = t >> 4;
    int arow = t >> 2, acol = (t & 3) << 2;
    int brow = t >> 4, bcol = (t & 15) << 2;
    float acc[4][4] = {};
    for (int k0 = 0; k0 < K; k0 += 16) {
        float4 av = make_float4(0.f,0.f,0.f,0.f);
        if (m0 + arow < M)
            av = *(const float4*)(A + (size_t)(m0+arow)*K + k0 + acol);
        As[acol  ][arow] = av.x; As[acol+1][arow] = av.y;
        As[acol+2][arow] = av.z; As[acol+3][arow] = av.w;
        *(float4*)(&Bs[brow][bcol]) =
            *(const float4*)(B + (size_t)(k0+brow)*N + n0 + bcol);
        __syncthreads();
        #pragma unroll
        for (int k = 0; k < 16; k++) {
            float4 a4 = *(const float4*)(&As[k][ty<<2]);
            float4 b4 = *(const float4*)(&Bs[k][tx<<2]);
            float avv[4] = {a4.x,a4.y,a4.z,a4.w};
            float bvv[4] = {b4.x,b4.y,b4.z,b4.w};
            #pragma unroll
            for (int i = 0; i < 4; i++)
                #pragma unroll
                for (int j = 0; j < 4; j++)
                    acc[i][j] = fmaf(avv[i], bvv[j], acc[i][j]);
        }
        __syncthreads();
    }
    float4 bv = *(const float4*)(bias + n0 + (tx<<2));
    #pragma unroll
    for (int i = 0; i < 4; i++) {
        int m = m0 + (ty<<2) + i;
        if (m >= M) break;
        float4 v = make_float4(acc[i][0]+bv.x, acc[i][1]+bv.y,
                               acc[i][2]+bv.z, acc[i][3]+bv.w);
        if (flags & FLAG_RELU) {
            v.x = fmaxf(v.x,0.f); v.y = fmaxf(v.y,0.f);
            v.z = fmaxf(v.z,0.f); v.w = fmaxf(v.w,0.f);
        }
        float4* cp = (float4*)(C + (size_t)m*N + n0 + (tx<<2));
        if (flags & FLAG_ADD) {
            float4 o = *cp;
            v.x += o.x; v.y += o.y; v.z += o.z; v.w += o.w;
        }
        *cp = v;
    }
}

// ---------------- layernorm (one block per row) ----------------
__global__ void ln_kernel(const float* __restrict__ x, float* __restrict__ y,
                          const float* __restrict__ g, const float* __restrict__ b) {
    int row = blockIdx.x, t = threadIdx.x;     // 256 threads
    const float* xr = x + (size_t)row*DIMM;
    float v0 = xr[t], v1 = xr[t+256];
    float2 s = blockReduce2_256(v0+v1, v0*v0+v1*v1);
    float mean = s.x * (1.f/512.f);
    float inv  = rsqrtf(s.y*(1.f/512.f) - mean*mean + 1e-5f);
    y[(size_t)row*DIMM + t]       = (v0-mean)*inv*g[t]     + b[t];
    y[(size_t)row*DIMM + t + 256] = (v1-mean)*inv*g[t+256] + b[t+256];
}

// ---------------- QK^T scores (per-head 32x32 tiles) ----------------
__global__ void scores_kernel() {
    __shared__ float sq[32][65];
    __shared__ float sk[32][65];
    int h  = blockIdx.z;
    int i0 = blockIdx.y << 5, j0 = blockIdx.x << 5;
    int t  = threadIdx.x;                 // 256 threads
    int r = t >> 3, c = (t & 7) << 3;
    {
        const float* qp = g_qkv + (size_t)(i0+r)*QKV3 + h*HDIM + c;
        const float* kp = g_qkv + (size_t)(j0+r)*QKV3 + DIMM + h*HDIM + c;
        bool qi = (i0 + r < NTOK), ki = (j0 + r < NTOK);
        #pragma unroll
        for (int q = 0; q < 8; q++) sq[r][c+q] = qi ? qp[q] : 0.f;
        #pragma unroll
        for (int q = 0; q < 8; q++) sk[r][c+q] = ki ? kp[q] : 0.f;
    }
    __syncthreads();
    int tx = t & 31, ty = t >> 5;        // ty in 0..7
    float acc[4] = {0.f,0.f,0.f,0.f};
    #pragma unroll
    for (int d = 0; d < 64; d++) {
        float kv = sk[tx][d];
        acc[0] = fmaf(sq[ty     ][d], kv, acc[0]);
        acc[1] = fmaf(sq[ty +  8][d], kv, acc[1]);
        acc[2] = fmaf(sq[ty + 16][d], kv, acc[2]);
        acc[3] = fmaf(sq[ty + 24][d], kv, acc[3]);
    }
    int j = j0 + tx;
    if (j < NTOK) {
        #pragma unroll
        for (int ii = 0; ii < 4; ii++) {
            int i = i0 + ty + (ii<<3);
            if (i < NTOK)
                g_attn[((size_t)h*NTOK + i)*NTOK + j] = 0.125f*acc[ii];
        }
    }
}

// ---------------- softmax over j, one block per (h,i) row ----------------
__global__ void softmax_kernel() {
    int row = blockIdx.x;                 // h*NTOK + i
    float* a = g_attn + (size_t)row*NTOK;
    int t = threadIdx.x;                  // 128 threads
    float vals[4];
    float mx = -1e30f;
    #pragma unroll
    for (int q = 0; q < 4; q++) {
        int j = t + q*128;
        vals[q] = (j < NTOK) ? a[j] : -1e30f;
        mx = fmaxf(mx, vals[q]);
    }
    #pragma unroll
    for (int o = 16; o > 0; o >>= 1)
        mx = fmaxf(mx, __shfl_xor_sync(0xffffffffu, mx, o));
    __shared__ float sm[4];
    if ((t & 31) == 0) sm[t >> 5] = mx;
    __syncthreads();
    mx = fmaxf(fmaxf(sm[0], sm[1]), fmaxf(sm[2], sm[3]));

    float s = 0.f;
    #pragma unroll
    for (int q = 0; q < 4; q++) {
        int j = t + q*128;
        if (j < NTOK) { vals[q] = __expf(vals[q] - mx); s += vals[q]; }
    }
    #pragma unroll
    for (int o = 16; o > 0; o >>= 1)
        s += __shfl_xor_sync(0xffffffffu, s, o);
    __shared__ float ss[4];
    if ((t & 31) == 0) ss[t >> 5] = s;
    __syncthreads();
    s = ss[0] + ss[1] + ss[2] + ss[3];
    float inv = 1.f / s;
    #pragma unroll
    for (int q = 0; q < 4; q++) {
        int j = t + q*128;
        if (j < NTOK) a[j] = vals[q] * inv;
    }
}

// ---------------- attn @ V  (per-head, 32 i-rows per block) ----------------
__global__ void av_kernel() {
    __shared__ float sa[32][33];
    __shared__ float sv[32][65];
    int h  = blockIdx.y;
    int i0 = blockIdx.x << 5;
    int t  = threadIdx.x;                 // 256 threads
    int d = t & 63, il = t >> 6;          // il in 0..3
    int ar = t >> 3, ac = (t & 7) << 2;
    int vr = t >> 3, vc = (t & 7) << 3;
    float acc[8] = {0.f,0.f,0.f,0.f,0.f,0.f,0.f,0.f};
    for (int j0 = 0; j0 < NTOK; j0 += 32) {
        #pragma unroll
        for (int q = 0; q < 4; q++) {
            int i = i0 + ar, j = j0 + ac + q;
            sa[ar][ac+q] = (i < NTOK && j < NTOK)
                         ? g_attn[((size_t)h*NTOK + i)*NTOK + j] : 0.f;
        }
        const float* vp = g_qkv + (size_t)(j0+vr)*QKV3 + 2*DIMM + h*HDIM + vc;
        bool vi = (j0 + vr < NTOK);
        #pragma unroll
        for (int q = 0; q < 8; q++) sv[vr][vc+q] = vi ? vp[q] : 0.f;
        __syncthreads();
        #pragma unroll
        for (int j = 0; j < 32; j++) {
            float vv = sv[j][d];
            #pragma unroll
            for (int ii = 0; ii < 8; ii++)
                acc[ii] = fmaf(sa[il + (ii<<2)][j], vv, acc[ii]);
        }
        __syncthreads();
    }
    #pragma unroll
    for (int ii = 0; ii < 8; ii++) {
        int i = i0 + il + (ii<<2);
        if (i < NTOK) g_ao[(size_t)i*DIMM + h*HDIM + d] = acc[ii];
    }
}

// ---------------- final: LN(row 0) -> fc2 -> out[2] ----------------
__global__ void final_kernel(const float* __restrict__ g, const float* __restrict__ b,
                             const float* __restrict__ w, const float* __restrict__ bias,
                             float* __restrict__ out) {
    int t = threadIdx.x;                  // 256 threads
    float v0 = g_h[t], v1 = g_h[t+256];
    float2 s = blockReduce2_256(v0+v1, v0*v0+v1*v1);
    float mean = s.x * (1.f/512.f);
    float inv  = rsqrtf(s.y*(1.f/512.f) - mean*mean + 1e-5f);
    float l0 = (v0-mean)*inv*g[t]     + b[t];
    float l1 = (v1-mean)*inv*g[t+256] + b[t+256];
    float p0 = l0*w[t*2]   + l1*w[(t+256)*2];
    float p1 = l0*w[t*2+1] + l1*w[(t+256)*2+1];
    float2 sp = blockReduce2_256(p0, p1);
    if (t == 0) { out[0] = sp.x + bias[0]; out[1] = sp.y + bias[1]; }
}

// ---------------- launch ----------------
extern "C" void kernel_launch(void* const* d_in, const int* in_sizes, int n_in,
                              void* d_out, int out_size) {
    const float* h_in   = (const float*)d_in[0];
    const float* coords = (const float*)d_in[1];
    const float* fc1_w  = (const float*)d_in[2];
    const float* fc1_b  = (const float*)d_in[3];
    const float* cls    = (const float*)d_in[4];
    const float* norm_g = (const float*)d_in[25];
    const float* norm_b = (const float*)d_in[26];
    const float* fc2_w  = (const float*)d_in[27];
    const float* fc2_b  = (const float*)d_in[28];

    float *p_h, *p_ln, *p_qkv, *p_ao;
    cudaGetSymbolAddress((void**)&p_h,   g_h);
    cudaGetSymbolAddress((void**)&p_ln,  g_ln);
    cudaGetSymbolAddress((void**)&p_qkv, g_qkv);
    cudaGetSymbolAddress((void**)&p_ao,  g_ao);

    setup_kernel<<<4, 256>>>(cls, coords);
    angpos_kernel<<<(NPAIR + 255)/256, 256>>>();
    // fc1 + relu into rows 1..400 of residual stream
    gemm_kernel<<<dim3(DIMM/64, (NPT+63)/64), 256>>>(
        h_in, fc1_w, fc1_b, p_h + DIMM, NPT, DIMM, 1024, FLAG_RELU);

    for (int L = 0; L < 2; L++) {
        const float* lp[10];
        for (int q = 0; q < 10; q++) lp[q] = (const float*)d_in[5 + L*10 + q];
        const float* ln_g   = lp[0]; const float* ln_b   = lp[1];
        const float* cpb_w1 = lp[2]; const float* cpb_b1 = lp[3];
        const float* cpb_w2 = lp[4]; const float* cpb_b2 = lp[5];
        const float* qkv_w  = lp[6]; const float* qkv_b  = lp[7];
        const float* proj_w = lp[8]; const float* proj_b = lp[9];

        cpb_table_kernel<<<(TABN + 3 + 255)/256, 256>>>(cpb_w1, cpb_b1, cpb_w2, cpb_b2);
        ln_kernel<<<NTOK, 256>>>(p_h, p_ln, ln_g, ln_b);
        gemm_kernel<<<dim3(QKV3/64, (NTOK+63)/64), 256>>>(
            p_ln, qkv_w, qkv_b, p_qkv, NTOK, QKV3, DIMM, 0);
        scores_kernel<<<dim3(13, 13, NHEAD), 256>>>();
        cpb_apply_kernel<<<(NPAIR + 255)/256, 256>>>();
        softmax_kernel<<<NHEAD*NTOK, 128>>>();
        av_kernel<<<dim3(13, NHEAD), 256>>>();
        gemm_kernel<<<dim3(DIMM/64, (NTOK+63)/64), 256>>>(
            p_ao, proj_w, proj_b, p_h, NTOK, DIMM, DIMM, FLAG_ADD);
    }

    final_kernel<<<1, 256>>>(norm_g, norm_b, fc2_w, fc2_b, (float*)d_out);
}